// round 8
// baseline (speedup 1.0000x reference)
#include <cuda_runtime.h>
#include <cuda_bf16.h>
#include <cstdint>

// labels [16, 8, 512, 512] f32 -> scalar f32
//   opened = grey_opening(labels, size=2); out = mean((labels - opened)^2)
// size=2: erosion e[i]=min(x[i-1],x[i]) (clamp at 0); dilation o[i]=max(e[i],e[i+1]) (clamp at H-1).
// This round: cp.async.bulk (UBLKCP) producer into a 5-slot smem ring.
// CTA = one 64-row x 512-col band (128KB contiguous in gmem). Bulk copies give the
// DRAM long contiguous bursts and hold ~32KB/CTA in flight at zero register/issue
// cost; consumers read rows from smem and run the separable min/max pipeline.

#define IMG_H   512
#define IMG_W   512
#define BANDS   8
#define N_BLK   1024              // 128 img * 8 bands
#define TPB     128               // thread owns 4 cols for the whole band
#define S       5                 // ring slots
#define STG_ROWS 4
#define ROWB    2048              // bytes per image row
#define TOTAL_ELEMS 33554432.0

__device__ double       g_partials[N_BLK];
__device__ unsigned int g_tickets = 0;   // reset by last block -> graph-replay safe

__device__ __forceinline__ uint32_t smem_u32(const void* p) {
    return (uint32_t)__cvta_generic_to_shared(p);
}
__device__ __forceinline__ void mbar_init(uint32_t a, uint32_t count) {
    asm volatile("mbarrier.init.shared.b64 [%0], %1;" :: "r"(a), "r"(count) : "memory");
}
__device__ __forceinline__ void mbar_arrive(uint32_t a) {
    asm volatile("mbarrier.arrive.shared.b64 _, [%0];" :: "r"(a) : "memory");
}
__device__ __forceinline__ void mbar_expect_tx(uint32_t a, uint32_t bytes) {
    asm volatile("mbarrier.arrive.expect_tx.shared.b64 _, [%0], %1;"
                 :: "r"(a), "r"(bytes) : "memory");
}
__device__ __forceinline__ void mbar_wait(uint32_t a, uint32_t parity) {
    uint32_t done;
    asm volatile(
        "{\n\t.reg .pred p;\n\t"
        "mbarrier.try_wait.parity.acquire.cta.shared::cta.b64 p, [%1], %2;\n\t"
        "selp.b32 %0, 1, 0, p;\n\t}"
        : "=r"(done) : "r"(a), "r"(parity) : "memory");
    if (!done) {
        asm volatile(
            "{\n\t.reg .pred P1;\n\t"
            "W0_%=:\n\t"
            "mbarrier.try_wait.parity.acquire.cta.shared::cta.b64 P1, [%0], %1, 0x989680;\n\t"
            "@P1 bra.uni W1_%=;\n\t"
            "bra.uni W0_%=;\n\t"
            "W1_%=:\n\t}"
            :: "r"(a), "r"(parity) : "memory");
    }
}
__device__ __forceinline__ void bulk_g2s(uint32_t dst, const void* src,
                                         uint32_t bytes, uint32_t mbar) {
    asm volatile(
        "cp.async.bulk.shared::cta.global.mbarrier::complete_tx::bytes [%0], [%1], %2, [%3];"
        :: "r"(dst), "l"(src), "r"(bytes), "r"(mbar) : "memory");
}

__global__ void __launch_bounds__(TPB, 5)
opening_mse_kernel(const float* __restrict__ x, float* __restrict__ out) {
    __shared__ __align__(16) float ring[S][STG_ROWS][IMG_W];   // 40 KB
    __shared__ __align__(8)  unsigned long long full_b[S], empty_b[S];
    __shared__ float  ws[TPB / 32];
    __shared__ double wd[TPB / 32];
    __shared__ int    s_last;

    const int tid  = threadIdx.x;
    const int lane = tid & 31;
    const int cta  = blockIdx.x;
    const int img  = cta >> 3;
    const int band = cta & 7;
    const int r0   = band << 6;
    const bool top = (band == 0), bot = (band == BANDS - 1);
    const int gstart  = top ? 0 : r0 - 1;
    const int nload   = (top || bot) ? 65 : 66;   // rows this CTA streams
    const int nstages = (nload + 3) >> 2;         // 17
    const int nsteps  = bot ? 65 : 66;            // consume steps
    const unsigned FULL = 0xffffffffu;

    const float* __restrict__ gband =
        x + (size_t)img * (IMG_H * IMG_W) + (size_t)gstart * IMG_W;

    if (tid == 0) {
        #pragma unroll
        for (int s = 0; s < S; s++) {
            mbar_init(smem_u32(&full_b[s]),  1);
            mbar_init(smem_u32(&empty_b[s]), TPB);
        }
    }
    __syncthreads();

    auto issue = [&](int k) {
        int rows = nload - (k << 2); if (rows > STG_ROWS) rows = STG_ROWS;
        uint32_t bytes = (uint32_t)rows << 11;
        uint32_t fb = smem_u32(&full_b[k % S]);
        mbar_expect_tx(fb, bytes);
        bulk_g2s(smem_u32(&ring[k % S][0][0]), gband + ((size_t)(k << 2)) * IMG_W,
                 bytes, fb);
    };

    if (tid == 0) {
        #pragma unroll
        for (int k = 0; k < S; k++) issue(k);   // fill the ring
    }
    mbar_wait(smem_u32(&full_b[0]), 0);

    float rm_prev[5], hprev[4], xbuf[4];
    float acc = 0.f;
    int cur = 0;

    #pragma unroll 2
    for (int j = 0; j < nsteps; j++) {
        const int off = top ? (j ? j - 1 : 0) : j;   // load-offset of this step's row
        const int s   = off >> 2;
        if (s != cur) {
            mbar_arrive(smem_u32(&empty_b[cur % S]));        // done with stage `cur`
            if (tid == 0) {
                int k = s + S - 1;                           // refill the freed slot
                if (k < nstages) {
                    mbar_wait(smem_u32(&empty_b[k % S]), ((k / S) - 1) & 1);
                    issue(k);
                }
            }
            mbar_wait(smem_u32(&full_b[s % S]), (s / S) & 1);
            cur = s;
        }

        const float* rp = &ring[s % S][off & 3][0];
        float4 a = *reinterpret_cast<const float4*>(rp + 4 * tid);
        float l = __shfl_up_sync(FULL, a.w, 1);
        float r = __shfl_down_sync(FULL, a.x, 1);
        if (lane == 0)  l = (tid == 0)       ? a.x : rp[4 * tid - 1];  // erosion left pad
        if (lane == 31) r = (tid == TPB - 1) ? 0.f : rp[4 * tid + 4];

        float rm[5];
        rm[0] = fminf(l,   a.x); rm[1] = fminf(a.x, a.y);
        rm[2] = fminf(a.y, a.z); rm[3] = fminf(a.z, a.w);
        rm[4] = fminf(a.w, r);
        if (tid == TPB - 1) rm[4] = rm[3];   // dilation right pad: er[512]=er[511]

        if (j == 0) {
            #pragma unroll
            for (int k = 0; k < 5; k++) rm_prev[k] = rm[k];
            continue;
        }
        float er[5];
        #pragma unroll
        for (int k = 0; k < 5; k++) { er[k] = fminf(rm_prev[k], rm[k]); rm_prev[k] = rm[k]; }
        float h[4];
        #pragma unroll
        for (int k = 0; k < 4; k++) h[k] = fmaxf(er[k], er[k + 1]);

        if (j >= 2) {
            #pragma unroll
            for (int k = 0; k < 4; k++) {
                float o = fmaxf(hprev[k], h[k]);
                float d = xbuf[k] - o;
                acc = fmaf(d, d, acc);
            }
        }
        #pragma unroll
        for (int k = 0; k < 4; k++) hprev[k] = h[k];
        xbuf[0] = a.x; xbuf[1] = a.y; xbuf[2] = a.z; xbuf[3] = a.w;
    }

    if (bot) {  // bottom pad: opened row 511 = hmax(eroded row 511) = hprev
        #pragma unroll
        for (int k = 0; k < 4; k++) {
            float d = xbuf[k] - hprev[k];
            acc = fmaf(d, d, acc);
        }
    }

    // ---- block reduction (deterministic: fixed tree, no float atomics) ----
    #pragma unroll
    for (int off = 16; off > 0; off >>= 1)
        acc += __shfl_down_sync(FULL, acc, off);
    if (lane == 0) ws[tid >> 5] = acc;
    __syncthreads();
    if (tid == 0) {
        float ssum = 0.f;
        #pragma unroll
        for (int w = 0; w < TPB / 32; w++) ssum += ws[w];
        g_partials[blockIdx.x] = (double)ssum;
        __threadfence();
        unsigned tick = atomicAdd(&g_tickets, 1u);
        s_last = (tick == N_BLK - 1);
    }
    __syncthreads();

    // ---- last block: fold 1024 partials, deterministic order ----
    if (s_last) {
        __threadfence();
        double d = 0.0;
        #pragma unroll 4
        for (int j = tid; j < N_BLK; j += TPB) d += g_partials[j];
        #pragma unroll
        for (int off = 16; off > 0; off >>= 1)
            d += __shfl_down_sync(FULL, d, off);
        if (lane == 0) wd[tid >> 5] = d;
        __syncthreads();
        if (tid == 0) {
            double tot = 0.0;
            #pragma unroll
            for (int w = 0; w < TPB / 32; w++) tot += wd[w];
            out[0] = (float)(tot / TOTAL_ELEMS);
            g_tickets = 0;   // reset for next graph replay
        }
    }
}

extern "C" void kernel_launch(void* const* d_in, const int* in_sizes, int n_in,
                              void* d_out, int out_size) {
    (void)in_sizes; (void)n_in; (void)out_size;
    const float* labels = (const float*)d_in[0];
    float* out = (float*)d_out;
    opening_mse_kernel<<<N_BLK, TPB>>>(labels, out);
}

// round 14
// speedup vs baseline: 1.9084x; 1.9084x over previous
#include <cuda_runtime.h>
#include <cuda_bf16.h>
#include <cuda_pipeline.h>

// labels [16, 8, 512, 512] f32 -> scalar f32
//   opened = grey_opening(labels, size=2); out = mean((labels - opened)^2)
// size=2: erosion e[i]=min(x[i-1],x[i]) (clamp at 0); dilation o[i]=max(e[i],e[i+1]) (clamp at H-1).
// Round 9 design: full-width band CTAs (zero column-halo overhead) + per-thread
// cp.async row ring (each thread streams its own 16B/row; a row = one coalesced
// 2KB volley). No mbarriers, no polling: wait_group + __syncthreads per row.

#define IMG_H   512
#define IMG_W   512
#define BANDS   8
#define N_BLK   1024              // 128 img * 8 bands
#define TPB     128               // thread owns 4 cols
#define R       8                 // ring slots (rows); R-2 = 6 rows in flight
#define TOTAL_ELEMS 33554432.0

__device__ double       g_partials[N_BLK];
__device__ unsigned int g_tickets = 0;   // reset by last block -> graph-replay safe

__global__ void __launch_bounds__(TPB, 7)
opening_mse_kernel(const float* __restrict__ x, float* __restrict__ out) {
    __shared__ __align__(16) float ring[R][IMG_W];   // 16 KB
    __shared__ float  ws[TPB / 32];
    __shared__ double wd[TPB / 32];
    __shared__ int    s_last;

    const int tid  = threadIdx.x;
    const int lane = tid & 31;
    const int cta  = blockIdx.x;
    const int img  = cta >> 3;
    const int band = cta & 7;
    const int r0   = band << 6;
    const bool top = (band == 0), bot = (band == BANDS - 1);
    const int gstart = top ? 0 : r0 - 1;
    const int nload  = (top || bot) ? 65 : 66;   // input rows this CTA streams
    const int nsteps = bot ? 65 : 66;            // consume iterations
    const unsigned FULL = 0xffffffffu;

    const float* __restrict__ gband =
        x + (size_t)img * (IMG_H * IMG_W) + (size_t)gstart * IMG_W;

    // issue loaded-row k: thread copies its own 16B piece into slot k%R
    auto issue = [&](int k) {
        __pipeline_memcpy_async(&ring[k & (R - 1)][4 * tid],
                                gband + (size_t)k * IMG_W + 4 * tid, 16);
    };

    // prologue: rows 0..R-3 in flight (one commit group per row)
    #pragma unroll
    for (int k = 0; k < R - 2; k++) { issue(k); __pipeline_commit(); }
    int nextk = R - 2;

    float rm_prev[5], hprev[4], xbuf[4];
    float acc = 0.f;

    for (int j = 0; j < nsteps; j++) {
        const int off = top ? (j ? j - 1 : 0) : j;   // loaded-row index consumed this iter

        __syncthreads();                  // all threads done consuming row off-1
        int k = off + R - 2;              // candidate issue (slot freed >=2 bars ago)
        if (k == nextk && k < nload) { issue(k); nextk++; }
        __pipeline_commit();              // exactly one group per iteration
        __pipeline_wait_prior(R - 2);     // loaded row `off` complete (own pieces)
        __syncthreads();                  // everyone's pieces of row `off` visible

        const float* rp = &ring[off & (R - 1)][0];
        float4 a = *reinterpret_cast<const float4*>(rp + 4 * tid);
        float l = __shfl_up_sync(FULL, a.w, 1);
        float r = __shfl_down_sync(FULL, a.x, 1);
        if (lane == 0)  l = (tid == 0)       ? a.x : rp[4 * tid - 1];  // erosion left pad
        if (lane == 31) r = (tid == TPB - 1) ? 0.f : rp[4 * tid + 4];

        float rm[5];
        rm[0] = fminf(l,   a.x); rm[1] = fminf(a.x, a.y);
        rm[2] = fminf(a.y, a.z); rm[3] = fminf(a.z, a.w);
        rm[4] = fminf(a.w, r);
        if (tid == TPB - 1) rm[4] = rm[3];   // dilation right pad: er[512]=er[511]

        if (j == 0) {
            #pragma unroll
            for (int q = 0; q < 5; q++) rm_prev[q] = rm[q];
            continue;
        }
        float er[5];
        #pragma unroll
        for (int q = 0; q < 5; q++) { er[q] = fminf(rm_prev[q], rm[q]); rm_prev[q] = rm[q]; }
        float h[4];
        #pragma unroll
        for (int q = 0; q < 4; q++) h[q] = fmaxf(er[q], er[q + 1]);

        if (j >= 2) {
            #pragma unroll
            for (int q = 0; q < 4; q++) {
                float o = fmaxf(hprev[q], h[q]);
                float d = xbuf[q] - o;
                acc = fmaf(d, d, acc);
            }
        }
        #pragma unroll
        for (int q = 0; q < 4; q++) hprev[q] = h[q];
        xbuf[0] = a.x; xbuf[1] = a.y; xbuf[2] = a.z; xbuf[3] = a.w;
    }

    if (bot) {  // bottom pad: opened row 511 = hprev
        #pragma unroll
        for (int q = 0; q < 4; q++) {
            float d = xbuf[q] - hprev[q];
            acc = fmaf(d, d, acc);
        }
    }

    // ---- block reduction (deterministic: fixed tree, no float atomics) ----
    #pragma unroll
    for (int off2 = 16; off2 > 0; off2 >>= 1)
        acc += __shfl_down_sync(FULL, acc, off2);
    if (lane == 0) ws[tid >> 5] = acc;
    __syncthreads();
    if (tid == 0) {
        float ssum = 0.f;
        #pragma unroll
        for (int w = 0; w < TPB / 32; w++) ssum += ws[w];
        g_partials[blockIdx.x] = (double)ssum;
        __threadfence();
        unsigned tick = atomicAdd(&g_tickets, 1u);
        s_last = (tick == N_BLK - 1);
    }
    __syncthreads();

    // ---- last block: fold 1024 partials, deterministic order ----
    if (s_last) {
        __threadfence();
        double d = 0.0;
        #pragma unroll 4
        for (int j2 = tid; j2 < N_BLK; j2 += TPB) d += g_partials[j2];
        #pragma unroll
        for (int off2 = 16; off2 > 0; off2 >>= 1)
            d += __shfl_down_sync(FULL, d, off2);
        if (lane == 0) wd[tid >> 5] = d;
        __syncthreads();
        if (tid == 0) {
            double tot = 0.0;
            #pragma unroll
            for (int w = 0; w < TPB / 32; w++) tot += wd[w];
            out[0] = (float)(tot / TOTAL_ELEMS);
            g_tickets = 0;   // reset for next graph replay
        }
    }
}

extern "C" void kernel_launch(void* const* d_in, const int* in_sizes, int n_in,
                              void* d_out, int out_size) {
    (void)in_sizes; (void)n_in; (void)out_size;
    const float* labels = (const float*)d_in[0];
    float* out = (float*)d_out;
    opening_mse_kernel<<<N_BLK, TPB>>>(labels, out);
}